// round 8
// baseline (speedup 1.0000x reference)
#include <cuda_runtime.h>
#include <math.h>

#define D 1024
#define D4 256            // D / 4
#define BPM 148           // blocks per module in stream phase
#define NBLK 296          // total blocks = one full wave at 2 CTAs/SM
#define KCH0 64           // W_alpha chunks per module (phase 0)
#define KR0 (D / KCH0)    // 16 rows per chunk
#define KCH2 128          // W_sum chunks per module (phase 2)
#define KR2 (D / KCH2)    // 8 rows per chunk

typedef unsigned long long u64;

// ---------------- scratch ----------------------------------------------------
__device__ float g_vm_partial[2][KCH2][D];   // GEMV partials (both stages)
__device__ float g_bw[2][D];                 // b_w per module
__device__ float g_main_partial[2][BPM][D];  // weighted-sum partials
__device__ float g_main_alpha[2][BPM];       // alpha-sum partials
__device__ float g_attn[2 * D];              // concat(res_in, res_out)
__device__ unsigned g_cnt[8];                // phase counters (zeroed per run)

// packed f32x2 FMA (SASS FFMA2; PTX-only)
__device__ __forceinline__ void fma2(u64& d, u64 a, u64 b) {
    asm("fma.rn.f32x2 %0, %1, %2, %0;" : "+l"(d) : "l"(a), "l"(b));
}
__device__ __forceinline__ u64 pack2(float lo, float hi) {
    u64 r; asm("mov.b64 %0, {%1, %2};" : "=l"(r) : "f"(lo), "f"(hi)); return r;
}
__device__ __forceinline__ void unpack2(float& lo, float& hi, u64 v) {
    asm("mov.b64 {%0, %1}, %2;" : "=f"(lo), "=f"(hi) : "l"(v));
}
// streaming 16B load (LDG.E.CS.128) — X has zero reuse
__device__ __forceinline__ void ldcs128(u64& a, u64& b, const void* p) {
    asm("ld.global.cs.v2.u64 {%0, %1}, [%2];" : "=l"(a), "=l"(b) : "l"(p));
}

// grid barrier helpers: all blocks guaranteed co-resident (one wave)
__device__ __forceinline__ void phase_arrive(int idx) {
    __threadfence();
    __syncthreads();
    if (threadIdx.x == 0) atomicAdd(&g_cnt[idx], 1u);
}
__device__ __forceinline__ void phase_wait(int idx, unsigned tgt) {
    if (threadIdx.x == 0) {
        while (*((volatile unsigned*)&g_cnt[idx]) < tgt) __nanosleep(64);
        __threadfence();
    }
    __syncthreads();
}

__global__ void zero_cnt() {
    if (threadIdx.x < 8) g_cnt[threadIdx.x] = 0;
}

// ---------------- THE megakernel --------------------------------------------
__global__ void __launch_bounds__(256, 2)
mega(const float* __restrict__ Xin,  const float* __restrict__ Xout,
     const float* __restrict__ Wai,  const float* __restrict__ bai,
     const float* __restrict__ Wsi,  const float* __restrict__ Wao,
     const float* __restrict__ bao,  const float* __restrict__ Wso,
     const float* __restrict__ linW, const float* __restrict__ linb,
     float* __restrict__ out, int nrows) {

    __shared__ __align__(16) char s_raw[33 * 1024];
    int bid = blockIdx.x;
    int t = threadIdx.x, warp = t >> 5, lane = t & 31;

    // ============ PHASE 0a: b_w partials (128 blocks) ========================
    if (bid < 2 * KCH0) {
        int vec = bid >> 6, chunk = bid & 63, k0 = chunk * KR0;
        const float* v = vec ? bao : bai;
        const float4* M4 = (const float4*)(vec ? Wao : Wai);
        float4 acc = make_float4(0.f, 0.f, 0.f, 0.f);
#pragma unroll
        for (int kk = 0; kk < KR0; kk++) {
            float vk = __ldg(v + k0 + kk);
            float4 m = M4[(size_t)(k0 + kk) * D4 + t];
            acc.x = fmaf(vk, m.x, acc.x); acc.y = fmaf(vk, m.y, acc.y);
            acc.z = fmaf(vk, m.z, acc.z); acc.w = fmaf(vk, m.w, acc.w);
        }
        ((float4*)g_vm_partial[vec][chunk])[t] = acc;
        phase_arrive(0);
    }

    // ============ PHASE 0b: reduce -> g_bw (16 blocks) =======================
    if (bid < 16) {
        phase_wait(0, 2 * KCH0);
        int vec = bid >> 3, cb = bid & 7;
        int c4 = cb * 32 + lane;
        float4 (*s_m)[32] = (float4(*)[32])s_raw;
        int grp = warp;
        float4 acc = make_float4(0.f, 0.f, 0.f, 0.f);
#pragma unroll
        for (int c = grp; c < KCH0; c += 8) {
            float4 p = ((const float4*)g_vm_partial[vec][c])[c4];
            acc.x += p.x; acc.y += p.y; acc.z += p.z; acc.w += p.w;
        }
        s_m[grp][lane] = acc;
        __syncthreads();
        if (grp == 0) {
            float4 tot = s_m[0][lane];
#pragma unroll
            for (int w = 1; w < 8; w++) {
                float4 v = s_m[w][lane];
                tot.x += v.x; tot.y += v.y; tot.z += v.z; tot.w += v.w;
            }
            ((float4*)g_bw[vec])[c4] = tot;
        }
        phase_arrive(1);
    }

    // ============ PHASE 1: stream X (all 296 blocks) =========================
    phase_wait(1, 16);
    {
        int mod = (bid >= BPM) ? 1 : 0;
        int xb = bid - mod * BPM;
        const ulonglong2* X2 = (const ulonglong2*)(mod ? Xout : Xin);

        float4* s_red = (float4*)s_raw;                 // 2048 float4 = 32KB
        float*  s_alpha = (float*)(s_raw + 32768);

        u64 bw[16];
        {
            const ulonglong2* B2 = (const ulonglong2*)g_bw[mod];
#pragma unroll
            for (int i = 0; i < 8; i++) {
                ulonglong2 v = B2[lane + 32 * i];
                bw[2 * i] = v.x; bw[2 * i + 1] = v.y;
            }
        }
        u64 acc[16];
#pragma unroll
        for (int i = 0; i < 16; i++) acc[i] = 0ull;
        float asum = 0.f;

        int gw = xb * 8 + warp;
        const int NW = BPM * 8;
        for (int row = gw; row < nrows; row += NW) {
            const ulonglong2* xr = X2 + (size_t)row * 256;
            u64 r[16];
#pragma unroll
            for (int i = 0; i < 8; i++)
                ldcs128(r[2 * i], r[2 * i + 1], xr + lane + 32 * i);
            u64 d0 = 0ull, d1 = 0ull;
#pragma unroll
            for (int i = 0; i < 8; i++) {
                fma2(d0, r[2 * i],     bw[2 * i]);
                fma2(d1, r[2 * i + 1], bw[2 * i + 1]);
            }
            float a0, a1, b0, b1;
            unpack2(a0, a1, d0); unpack2(b0, b1, d1);
            float s = (a0 + a1) + (b0 + b1);
#pragma unroll
            for (int o = 16; o > 0; o >>= 1)
                s += __shfl_xor_sync(0xffffffffu, s, o);
            float alpha = __expf(s);     // lane-uniform
            asum += alpha;               // per-lane == warp total
            u64 alpha2 = pack2(alpha, alpha);
#pragma unroll
            for (int i = 0; i < 16; i++) fma2(acc[i], alpha2, r[i]);
        }

#pragma unroll
        for (int i = 0; i < 8; i++) {
            float x, y, z, w;
            unpack2(x, y, acc[2 * i]); unpack2(z, w, acc[2 * i + 1]);
            s_red[warp * D4 + lane + 32 * i] = make_float4(x, y, z, w);
        }
        if (lane == 0) s_alpha[warp] = asum;
        __syncthreads();
        float4 tot = make_float4(0.f, 0.f, 0.f, 0.f);
#pragma unroll
        for (int w = 0; w < 8; w++) {
            float4 v = s_red[w * D4 + t];
            tot.x += v.x; tot.y += v.y; tot.z += v.z; tot.w += v.w;
        }
        ((float4*)g_main_partial[mod][xb])[t] = tot;
        if (t == 0) {
            float a = 0.f;
#pragma unroll
            for (int w = 0; w < 8; w++) a += s_alpha[w];
            g_main_alpha[mod][xb] = a;
        }
        phase_arrive(2);
    }
    if (bid >= 2 * KCH2) return;   // blocks 256..295 done

    // ============ PHASE 2: W_sum GEMV partials (256 blocks) ==================
    phase_wait(2, NBLK);
    {
        int vec = bid >> 7, kc = bid & 127, k0 = kc * KR2;
        const float4* M4 = (const float4*)(vec ? Wso : Wsi);
        float4 m[KR2];
#pragma unroll
        for (int kk = 0; kk < KR2; kk++)
            m[kk] = M4[(size_t)(k0 + kk) * D4 + t];

        float (*s_t)[9] = (float(*)[9])s_raw;      // [32][9]
        float* s_v = (float*)(s_raw + 32 * 9 * 4);
        {
            int g = t & 7, i = t >> 3;             // 32 rowgroups x 8 cols
            float a = 0.f;
            for (int b = i; b < BPM; b += 32)
                a += g_main_partial[vec][b][k0 + g];
            s_t[i][g] = a;
        }
        __syncthreads();
        if (t < KR2) {
            float a = 0.f;
#pragma unroll
            for (int i = 0; i < 32; i++) a += s_t[i][t];
            s_v[t] = a;
        }
        __syncthreads();
        float4 acc = make_float4(0.f, 0.f, 0.f, 0.f);
#pragma unroll
        for (int kk = 0; kk < KR2; kk++) {
            float vk = s_v[kk];
            acc.x = fmaf(vk, m[kk].x, acc.x); acc.y = fmaf(vk, m[kk].y, acc.y);
            acc.z = fmaf(vk, m[kk].z, acc.z); acc.w = fmaf(vk, m[kk].w, acc.w);
        }
        ((float4*)g_vm_partial[vec][kc])[t] = acc;
        phase_arrive(3);
    }

    // ============ PHASE 3: reduce + 1/sum(alpha) -> g_attn (16 blocks) =======
    if (bid < 16) {
        phase_wait(3, 2 * KCH2);
        int vec = bid >> 3, cb = bid & 7;
        int c4 = cb * 32 + lane;
        float4 (*s_m)[32] = (float4(*)[32])s_raw;
        float* s_inv = (float*)(s_raw + 4096);
        if (t < 32) {
            float a = 0.f;
            for (int b = t; b < BPM; b += 32) a += g_main_alpha[vec][b];
#pragma unroll
            for (int o = 16; o > 0; o >>= 1)
                a += __shfl_xor_sync(0xffffffffu, a, o);
            if (t == 0) *s_inv = 1.0f / a;
        }
        int grp = warp;
        float4 acc = make_float4(0.f, 0.f, 0.f, 0.f);
#pragma unroll
        for (int c = grp; c < KCH2; c += 8) {
            float4 p = ((const float4*)g_vm_partial[vec][c])[c4];
            acc.x += p.x; acc.y += p.y; acc.z += p.z; acc.w += p.w;
        }
        s_m[grp][lane] = acc;
        __syncthreads();
        if (grp == 0) {
            float4 tot = s_m[0][lane];
#pragma unroll
            for (int w = 1; w < 8; w++) {
                float4 v = s_m[w][lane];
                tot.x += v.x; tot.y += v.y; tot.z += v.z; tot.w += v.w;
            }
            float inv = *s_inv;
            tot.x *= inv; tot.y *= inv; tot.z *= inv; tot.w *= inv;
            ((float4*)&g_attn[vec * D])[c4] = tot;
        }
        phase_arrive(4);
    }

    // ============ PHASE 4: out = elu(attn @ lin_W^T + lin_b) (256 blocks) ====
    phase_wait(4, 16);
    {
        float4* sa = (float4*)s_raw;               // 512 float4 = 8KB
        float*  sw = (float*)(s_raw + 8192);
        sa[t]       = ((const float4*)g_attn)[t];
        sa[t + D4]  = ((const float4*)g_attn)[t + D4];
        __syncthreads();
#pragma unroll
        for (int q = 0; q < 4; q++) {
            int i = bid * 4 + q;
            const float4* row = (const float4*)linW + (size_t)i * (2 * D4);
            float4 w1 = row[t],      a1 = sa[t];
            float4 w2 = row[t + D4], a2 = sa[t + D4];
            float s = 0.f;
            s = fmaf(w1.x, a1.x, s); s = fmaf(w1.y, a1.y, s);
            s = fmaf(w1.z, a1.z, s); s = fmaf(w1.w, a1.w, s);
            s = fmaf(w2.x, a2.x, s); s = fmaf(w2.y, a2.y, s);
            s = fmaf(w2.z, a2.z, s); s = fmaf(w2.w, a2.w, s);
#pragma unroll
            for (int o = 16; o > 0; o >>= 1)
                s += __shfl_xor_sync(0xffffffffu, s, o);
            if (lane == 0) sw[warp] = s;
            __syncthreads();
            if (t == 0) {
                float tot = 0.f;
#pragma unroll
                for (int w = 0; w < 8; w++) tot += sw[w];
                tot += linb[i];
                out[i] = tot > 0.f ? tot : expm1f(tot);   // ELU, alpha=1
            }
            __syncthreads();
        }
    }
}

// ---------------- launcher ----------------------------------------------------
extern "C" void kernel_launch(void* const* d_in, const int* in_sizes, int n_in,
                              void* d_out, int out_size) {
    const float* X_in      = (const float*)d_in[0];
    const float* X_out     = (const float*)d_in[1];
    const float* W_alpha_i = (const float*)d_in[2];
    // d_in[3] = a_alpha_in : unused (constant cancels in normalization)
    const float* b_alpha_i = (const float*)d_in[4];
    const float* W_sum_i   = (const float*)d_in[5];
    const float* W_alpha_o = (const float*)d_in[6];
    // d_in[7] = a_alpha_out : unused
    const float* b_alpha_o = (const float*)d_in[8];
    const float* W_sum_o   = (const float*)d_in[9];
    const float* lin_W     = (const float*)d_in[10];
    const float* lin_b     = (const float*)d_in[11];
    float* out = (float*)d_out;

    int nrows = in_sizes[0] / D;   // 50000

    zero_cnt<<<1, 32>>>();
    mega<<<NBLK, 256>>>(X_in, X_out,
                        W_alpha_i, b_alpha_i, W_sum_i,
                        W_alpha_o, b_alpha_o, W_sum_o,
                        lin_W, lin_b, out, nrows);
}

// round 10
// speedup vs baseline: 1.0570x; 1.0570x over previous
#include <cuda_runtime.h>
#include <math.h>

#define D 1024
#define D4 256          // D / 4
#define NROWS 50000
#define BPM 148         // blocks per module, main pass
#define NBLK 296
#define KCH0 64         // W_alpha chunks per module (stage-1 vecmat)
#define KR0 (D / KCH0)  // 16
#define KCH2 128        // W_sum chunks per module (stage-2 vecmat)
#define KR2 (D / KCH2)  // 8

typedef unsigned long long u64;

// ---------------- scratch (device globals; no allocation allowed) -----------
__device__ float g_vm_partial[2][KCH2][D];    // GEMV partials (both stages)
__device__ float g_bw[2][D];                  // b_w per module
__device__ float g_main_partial[2][BPM][D];   // weighted-sum partials
__device__ float g_main_alpha[2][BPM];        // alpha-sum partials
__device__ float g_attn[2 * D];               // concat(res_in, res_out)

// packed f32x2 FMA: d = a*b + d   (SASS FFMA2; PTX-only form)
__device__ __forceinline__ void fma2(u64& d, u64 a, u64 b) {
    asm("fma.rn.f32x2 %0, %1, %2, %0;" : "+l"(d) : "l"(a), "l"(b));
}
__device__ __forceinline__ u64 pack2(float lo, float hi) {
    u64 r; asm("mov.b64 %0, {%1, %2};" : "=l"(r) : "f"(lo), "f"(hi)); return r;
}
__device__ __forceinline__ void unpack2(float& lo, float& hi, u64 v) {
    asm("mov.b64 {%0, %1}, %2;" : "=f"(lo), "=f"(hi) : "l"(v));
}
// streaming 16B load (LDG.E.CS.128) — X has zero reuse
__device__ __forceinline__ void ldcs128(u64& a, u64& b, const void* p) {
    asm("ld.global.cs.v2.u64 {%0, %1}, [%2];" : "=l"(a), "=l"(b) : "l"(p));
}
// L2 warm: prefetch line into L2 with evict_last (no dest regs, no DCE issue)
__device__ __forceinline__ void l2warm(const void* p) {
    asm volatile("prefetch.global.L2::evict_last [%0];" :: "l"(p));
}
// PDL primitives
__device__ __forceinline__ void gdc_wait() {
    asm volatile("griddepcontrol.wait;" ::: "memory");
}
__device__ __forceinline__ void gdc_launch() {
    asm volatile("griddepcontrol.launch_dependents;" ::: "memory");
}

// ---------------- stage-1 vecmat: b_w = b_alpha^T @ W_alpha ------------------
__global__ void vecmat_partial(const float* __restrict__ v0,
                               const float* __restrict__ M0,
                               const float* __restrict__ v1,
                               const float* __restrict__ M1) {
    int vec = blockIdx.y;
    const float* v = vec ? v1 : v0;
    const float4* M4 = (const float4*)(vec ? M1 : M0);
    int t = threadIdx.x;
    int k0 = blockIdx.x * KR0;
    float4 acc = make_float4(0.f, 0.f, 0.f, 0.f);
#pragma unroll
    for (int kk = 0; kk < KR0; kk++) {
        float vk = __ldg(v + k0 + kk);
        float4 m = M4[(size_t)(k0 + kk) * D4 + t];
        acc.x = fmaf(vk, m.x, acc.x); acc.y = fmaf(vk, m.y, acc.y);
        acc.z = fmaf(vk, m.z, acc.z); acc.w = fmaf(vk, m.w, acc.w);
    }
    ((float4*)g_vm_partial[vec][blockIdx.x])[t] = acc;
    gdc_launch();
}

// ---------------- reduce vm partials -----------------------------------------
// which==0: nch=KCH0 -> g_bw ; which==1: nch=KCH2, scale by 1/sum(alpha) -> g_attn
__global__ void vecmat_reduce(int which, int nch) {
    int vec = blockIdx.y;
    int t = threadIdx.x, grp = t >> 5, lane = t & 31;
    int c4 = blockIdx.x * 32 + lane;

    __shared__ float4 s_m[8][32];
    __shared__ float  s_inv;

    if (which && t < 32) {
        float a = 0.f;
        for (int b = t; b < BPM; b += 32) a += g_main_alpha[vec][b];
#pragma unroll
        for (int o = 16; o > 0; o >>= 1)
            a += __shfl_xor_sync(0xffffffffu, a, o);
        if (t == 0) s_inv = 1.0f / a;
    }

    float4 acc = make_float4(0.f, 0.f, 0.f, 0.f);
    for (int c = grp; c < nch; c += 8) {
        float4 p = ((const float4*)g_vm_partial[vec][c])[c4];
        acc.x += p.x; acc.y += p.y; acc.z += p.z; acc.w += p.w;
    }
    s_m[grp][lane] = acc;
    __syncthreads();
    if (grp == 0) {
        float4 tot = s_m[0][lane];
#pragma unroll
        for (int w = 1; w < 8; w++) {
            float4 v = s_m[w][lane];
            tot.x += v.x; tot.y += v.y; tot.z += v.z; tot.w += v.w;
        }
        if (which) {
            float inv = s_inv;
            tot.x *= inv; tot.y *= inv; tot.z *= inv; tot.w *= inv;
            ((float4*)&g_attn[vec * D])[c4] = tot;
        } else {
            ((float4*)g_bw[vec])[c4] = tot;
        }
    }
    gdc_launch();
}

// ---------------- main single-pass kernel + L2 warm of tail weights ----------
__global__ void __launch_bounds__(256, 2)
main_pass(const float* __restrict__ Xin, const float* __restrict__ Xout,
          const float* __restrict__ Wsi, const float* __restrict__ Wso,
          const float* __restrict__ linW, int nrows) {
    int mod = (blockIdx.x >= BPM) ? 1 : 0;
    int xb = blockIdx.x - mod * BPM;
    const ulonglong2* X2 = (const ulonglong2*)(mod ? Xout : Xin);

    __shared__ float4 s_red[8 * D4];
    __shared__ float  s_alpha[8];

    int t = threadIdx.x, warp = t >> 5, lane = t & 31;

    gdc_wait();    // PSS: wait for vecmat_reduce(0) before reading g_bw

    u64 bw[16];
    {
        const ulonglong2* B2 = (const ulonglong2*)g_bw[mod];
#pragma unroll
        for (int i = 0; i < 8; i++) {
            ulonglong2 v = B2[lane + 32 * i];
            bw[2 * i] = v.x; bw[2 * i + 1] = v.y;
        }
    }

    u64 acc[16];
#pragma unroll
    for (int i = 0; i < 16; i++) acc[i] = 0ull;
    float asum = 0.f;

    int gw = xb * 8 + warp;
    const int NW = BPM * 8;

    for (int row = gw; row < nrows; row += NW) {
        const ulonglong2* xr = X2 + (size_t)row * 256;
        u64 r[16];
#pragma unroll
        for (int i = 0; i < 8; i++)
            ldcs128(r[2 * i], r[2 * i + 1], xr + lane + 32 * i);

        u64 d0 = 0ull, d1 = 0ull;
#pragma unroll
        for (int i = 0; i < 8; i++) {
            fma2(d0, r[2 * i],     bw[2 * i]);
            fma2(d1, r[2 * i + 1], bw[2 * i + 1]);
        }
        float a0, a1, b0, b1;
        unpack2(a0, a1, d0); unpack2(b0, b1, d1);
        float s = (a0 + a1) + (b0 + b1);
#pragma unroll
        for (int o = 16; o > 0; o >>= 1)
            s += __shfl_xor_sync(0xffffffffu, s, o);

        float alpha = __expf(s);                  // lane-uniform after butterfly
        asum += alpha;                            // per-lane asum == warp total
        u64 alpha2 = pack2(alpha, alpha);
#pragma unroll
        for (int i = 0; i < 16; i++) fma2(acc[i], alpha2, r[i]);
    }

    // deterministic block reduce
#pragma unroll
    for (int i = 0; i < 8; i++) {
        float x, y, z, w;
        unpack2(x, y, acc[2 * i]); unpack2(z, w, acc[2 * i + 1]);
        s_red[warp * D4 + lane + 32 * i] = make_float4(x, y, z, w);
    }
    if (lane == 0) s_alpha[warp] = asum;
    __syncthreads();

    float4 tot = make_float4(0.f, 0.f, 0.f, 0.f);
#pragma unroll
    for (int w = 0; w < 8; w++) {
        float4 v = s_red[w * D4 + t];
        tot.x += v.x; tot.y += v.y; tot.z += v.z; tot.w += v.w;
    }
    ((float4*)g_main_partial[mod][xb])[t] = tot;
    if (t == 0) {
        float a = 0.f;
#pragma unroll
        for (int w = 0; w < 8; w++) a += s_alpha[w];
        g_main_alpha[mod][xb] = a;
    }
    gdc_launch();   // signal dependents FIRST, then warm L2 in the idle tail

    // ---- L2 warm: W_sum_i, W_sum_o, lin_W (24 MB, one prefetch per 128B) ---
    {
        const char* pWsi = (const char*)Wsi;
        const char* pWso = (const char*)Wso;
        const char* pLin = (const char*)linW;
        const int NLINES = D * D * 4 / 128;       // 32768 lines per DxD matrix
        int l0 = blockIdx.x * 256 + t;
        const int LSTR = NBLK * 256;              // 75776
        for (int l = l0; l < NLINES; l += LSTR) {
            l2warm(pWsi + (size_t)l * 128);
            l2warm(pWso + (size_t)l * 128);
        }
        for (int l = l0; l < 2 * NLINES; l += LSTR)
            l2warm(pLin + (size_t)l * 128);
    }
}

// ---------------- stage-2 vecmat (256 blocks), PDL + L2-warm source ----------
__global__ void vecmat_so_partial(const float* __restrict__ M0,
                                  const float* __restrict__ M1) {
    int vec = blockIdx.y;
    const float4* M4 = (const float4*)(vec ? M1 : M0);
    int t = threadIdx.x;
    int k0 = blockIdx.x * KR2;

    gdc_wait();    // main_pass output (and its L2 warm) ready

    __shared__ float s_t[32][9];   // [rowgrp][col], padded
    __shared__ float s_v[KR2];

    // COALESCED column reduce: 32 rowgroups x 8 consecutive columns
    {
        int g = t & 7, i = t >> 3;
        float a = 0.f;
        for (int b = i; b < BPM; b += 32)
            a += g_main_partial[vec][b][k0 + g];
        s_t[i][g] = a;
    }
    __syncthreads();
    if (t < KR2) {
        float a = 0.f;
#pragma unroll
        for (int i = 0; i < 32; i++) a += s_t[i][t];
        s_v[t] = a;
    }
    __syncthreads();

    float4 acc = make_float4(0.f, 0.f, 0.f, 0.f);
#pragma unroll
    for (int kk = 0; kk < KR2; kk++) {           // W_sum rows now L2-resident
        float vk = s_v[kk];
        float4 m = M4[(size_t)(k0 + kk) * D4 + t];
        acc.x = fmaf(vk, m.x, acc.x); acc.y = fmaf(vk, m.y, acc.y);
        acc.z = fmaf(vk, m.z, acc.z); acc.w = fmaf(vk, m.w, acc.w);
    }
    ((float4*)g_vm_partial[vec][blockIdx.x])[t] = acc;
    gdc_launch();
}

// ---------------- final: out[i] = elu( lin_W[i,:] . attn + lin_b[i] ) -------
__global__ void final_kernel(const float* __restrict__ linW,
                             const float* __restrict__ linb,
                             float* __restrict__ out) {
    int t = threadIdx.x;
    int i = blockIdx.x;

    // lin_W row is L2-resident from the warm; load before the wait
    const float4* row = (const float4*)linW + (size_t)i * (2 * D4);
    float4 w1 = row[t];
    float4 w2 = row[t + D4];
    float  bias = linb[i];

    gdc_wait();    // g_attn now valid

    float4 a1 = ((const float4*)g_attn)[t];
    float4 a2 = ((const float4*)g_attn)[t + D4];
    float s = 0.f;
    s = fmaf(w1.x, a1.x, s); s = fmaf(w1.y, a1.y, s);
    s = fmaf(w1.z, a1.z, s); s = fmaf(w1.w, a1.w, s);
    s = fmaf(w2.x, a2.x, s); s = fmaf(w2.y, a2.y, s);
    s = fmaf(w2.z, a2.z, s); s = fmaf(w2.w, a2.w, s);

#pragma unroll
    for (int o = 16; o > 0; o >>= 1)
        s += __shfl_xor_sync(0xffffffffu, s, o);
    __shared__ float sw[8];
    int warp = t >> 5, lane = t & 31;
    if (lane == 0) sw[warp] = s;
    __syncthreads();
    if (t == 0) {
        float tot = 0.f;
#pragma unroll
        for (int w = 0; w < 8; w++) tot += sw[w];
        tot += bias;
        out[i] = tot > 0.f ? tot : expm1f(tot);   // jax.nn.elu, alpha=1
    }
}

// ---------------- PSS launch helper ------------------------------------------
static void launch_pss(const void* fn, dim3 grid, dim3 block, void** args) {
    cudaLaunchConfig_t cfg = {};
    cfg.gridDim = grid;
    cfg.blockDim = block;
    cfg.dynamicSmemBytes = 0;
    cfg.stream = 0;
    cudaLaunchAttribute at;
    at.id = cudaLaunchAttributeProgrammaticStreamSerialization;
    at.val.programmaticStreamSerializationAllowed = 1;
    cfg.attrs = &at;
    cfg.numAttrs = 1;
    cudaLaunchKernelExC(&cfg, fn, args);
}

// ---------------- launcher ---------------------------------------------------
extern "C" void kernel_launch(void* const* d_in, const int* in_sizes, int n_in,
                              void* d_out, int out_size) {
    const float* X_in      = (const float*)d_in[0];
    const float* X_out     = (const float*)d_in[1];
    const float* W_alpha_i = (const float*)d_in[2];
    // d_in[3] = a_alpha_in : unused (constant cancels in normalization)
    const float* b_alpha_i = (const float*)d_in[4];
    const float* W_sum_i   = (const float*)d_in[5];
    const float* W_alpha_o = (const float*)d_in[6];
    // d_in[7] = a_alpha_out : unused
    const float* b_alpha_o = (const float*)d_in[8];
    const float* W_sum_o   = (const float*)d_in[9];
    const float* lin_W     = (const float*)d_in[10];
    const float* lin_b     = (const float*)d_in[11];
    float* out = (float*)d_out;

    int nrows = in_sizes[0] / D;   // 50000

    // #1: b_w partials
    vecmat_partial<<<dim3(KCH0, 2), 256>>>(b_alpha_i, W_alpha_i,
                                           b_alpha_o, W_alpha_o);
    // #2: reduce -> g_bw
    int w0 = 0, n0 = KCH0, w1 = 1, n1 = KCH2;
    vecmat_reduce<<<dim3(8, 2), 256>>>(w0, n0);

    // #3: main pass (PSS) + L2 warm of W_sum/lin_W in its tail
    {
        const float* a = X_in; const float* b = X_out;
        const float* c = W_sum_i; const float* d = W_sum_o;
        const float* e = lin_W; int n = nrows;
        void* args[] = { (void*)&a, (void*)&b, (void*)&c,
                         (void*)&d, (void*)&e, (void*)&n };
        launch_pss((const void*)main_pass, dim3(NBLK), dim3(256), args);
    }

    // #4: fused column-reduce + GEMV vs W_sum (PSS, 256 blocks, L2 hits)
    {
        const float* a = W_sum_i; const float* b = W_sum_o;
        void* args[] = { (void*)&a, (void*)&b };
        launch_pss((const void*)vecmat_so_partial, dim3(KCH2, 2), dim3(256), args);
    }

    // #5: reduce + scale by 1/sum(alpha) -> g_attn
    vecmat_reduce<<<dim3(8, 2), 256>>>(w1, n1);

    // #6: final (PSS; lin_W L2-resident)
    {
        const float* a = lin_W; const float* b = lin_b; float* o = out;
        void* args[] = { (void*)&a, (void*)&b, (void*)&o };
        launch_pss((const void*)final_kernel, dim3(D), dim3(256), args);
    }
}